// round 1
// baseline (speedup 1.0000x reference)
#include <cuda_runtime.h>

#define C_IN   64
#define C_OUT  64
#define HW     256
#define OHW    512
#define TI     16
#define TH     17                       // tile + bottom/right halo
#define TILE_ELEMS (TH*TH)              // 289
#define XS_FLOATS  (C_IN*TILE_ELEMS)    // 18496
#define SMEM_BYTES (XS_FLOATS*4)        // 73984

// Packed per-parity weights: [branch(high/low)][parity][k*64 + o], K up to 4*64
__device__ float g_wpack[2][4][4*64*64];
__device__ float g_biaslow[4][C_OUT];

// -------------------------------------------------------------------------
// Prep: fold low1 (1x1) into low2 weights, pack both branches per parity.
// Parity p = py*2+px. Row taps: py==0 -> {(dy=0,ky=1)}; py==1 -> {(0,2),(1,0)}.
// Same for columns. Tap t = ty*ntx + tx.
// -------------------------------------------------------------------------
__global__ void pack_kernel(const float* __restrict__ high_w,
                            const float* __restrict__ low1_w,
                            const float* __restrict__ low1_b,
                            const float* __restrict__ low2_w,
                            const float* __restrict__ low2_b)
{
    const int branch = blockIdx.x;
    const int p  = blockIdx.y;
    const int py = p >> 1, px = p & 1;
    const int nty = py ? 2 : 1, ntx = px ? 2 : 1;
    const int K = nty * ntx * 64;

    for (int idx = threadIdx.x; idx < K*64; idx += blockDim.x) {
        int o = idx & 63;
        int k = idx >> 6;
        int c = k & 63;
        int t = k >> 6;
        int ty = t / ntx, tx = t % ntx;
        int ky = py ? (ty ? 0 : 2) : 1;
        int kx = px ? (tx ? 0 : 2) : 1;
        float w;
        if (branch == 0) {
            w = high_w[((c*64 + o)*3 + ky)*3 + kx];
        } else {
            float s = 0.f;
            #pragma unroll
            for (int r = 0; r < 16; ++r)
                s += low1_w[r*64 + c] * low2_w[((r*64 + o)*3 + ky)*3 + kx];
            w = s;
        }
        g_wpack[branch][p][idx] = w;
    }

    if (branch == 1 && threadIdx.x < 64) {
        int o = threadIdx.x;
        float s = low2_b[o];
        for (int ty = 0; ty < nty; ++ty)
            for (int tx = 0; tx < ntx; ++tx) {
                int ky = py ? (ty ? 0 : 2) : 1;
                int kx = px ? (tx ? 0 : 2) : 1;
                for (int r = 0; r < 16; ++r)
                    s += low1_b[r] * low2_w[((r*64 + o)*3 + ky)*3 + kx];
            }
        g_biaslow[p][o] = s;
    }
}

// -------------------------------------------------------------------------
// Main: per block, one (b, 16x16 input tile) -> 32x32 output tile, all 64
// out channels. 4 parity-class GEMMs over the shared x tile.
// Thread microtile: 8 out-ch x 8 pixels. Per-pixel branch select via FSEL.
// -------------------------------------------------------------------------
__global__ __launch_bounds__(256, 2)
void tconv_main(const float* __restrict__ x,
                const float* __restrict__ mask,
                const float* __restrict__ high_b,
                float* __restrict__ out)
{
    extern __shared__ float xs[];
    const int b   = blockIdx.z;
    const int y0  = blockIdx.y * TI;
    const int x0  = blockIdx.x * TI;
    const int tid = threadIdx.x;

    // Load x tile (+ bottom/right halo, zero-padded at image edge)
    const float* xg = x + (size_t)b * C_IN * HW * HW;
    for (int idx = tid; idx < XS_FLOATS; idx += 256) {
        int c  = idx / TILE_ELEMS;
        int s  = idx - c * TILE_ELEMS;
        int ry = s / TH;
        int rx = s - ry * TH;
        int iy = y0 + ry, ix = x0 + rx;
        float v = 0.f;
        if (iy < HW && ix < HW) v = xg[(c * HW + iy) * HW + ix];
        xs[idx] = v;
    }
    __syncthreads();

    const int og  = tid & 7;        // out-channel group: o = og*8 .. og*8+7
    const int pg  = tid >> 3;       // pixel group (32 groups of 8 pixels)
    const int yy  = pg >> 1;        // row within 16x16 parity subtile
    const int xx0 = (pg & 1) * 8;   // col base within subtile

    #pragma unroll 1
    for (int p = 0; p < 4; ++p) {
        const int py = p >> 1, px = p & 1;
        const int ntx = px ? 2 : 1;
        const int ntaps = (py ? 2 : 1) * ntx;
        const int oy  = 2*(y0 + yy) + py;
        const int oxb = 2*(x0 + xx0) + px;

        bool f[8];
        #pragma unroll
        for (int j = 0; j < 8; ++j) {
            float mv = mask[((size_t)b * OHW + oy) * OHW + oxb + 2*j];
            f[j] = (mv >= 0.5f);
        }

        float acc[8][8];
        #pragma unroll
        for (int o = 0; o < 8; ++o)
            #pragma unroll
            for (int j = 0; j < 8; ++j) acc[o][j] = 0.f;

        const float* wbh = &g_wpack[0][p][0] + og*8;
        const float* wbl = &g_wpack[1][p][0] + og*8;

        #pragma unroll 1
        for (int t = 0; t < ntaps; ++t) {
            const int ty = (ntx == 2) ? (t >> 1) : t;
            const int tx = (ntx == 2) ? (t & 1)  : 0;
            const float* xrow = xs + (yy + ty)*TH + xx0 + tx;
            const float* wh_t = wbh + t*64*64;
            const float* wl_t = wbl + t*64*64;

            #pragma unroll 1
            for (int c = 0; c < 64; ++c) {
                float4 h0 = *(const float4*)(wh_t + c*64);
                float4 h1 = *(const float4*)(wh_t + c*64 + 4);
                float4 l0 = *(const float4*)(wl_t + c*64);
                float4 l1 = *(const float4*)(wl_t + c*64 + 4);
                float wh[8] = {h0.x,h0.y,h0.z,h0.w,h1.x,h1.y,h1.z,h1.w};
                float wl[8] = {l0.x,l0.y,l0.z,l0.w,l1.x,l1.y,l1.z,l1.w};
                const float* xr = xrow + c*TILE_ELEMS;
                float xv[8];
                #pragma unroll
                for (int j = 0; j < 8; ++j) xv[j] = xr[j];
                #pragma unroll
                for (int j = 0; j < 8; ++j) {
                    const float xj = xv[j];
                    #pragma unroll
                    for (int o = 0; o < 8; ++o)
                        acc[o][j] = fmaf(xj, f[j] ? wh[o] : wl[o], acc[o][j]);
                }
            }
        }

        // Epilogue: add branch-selected bias, store strided-2 pixels
        #pragma unroll
        for (int o = 0; o < 8; ++o) {
            const int oc = og*8 + o;
            const float bh = __ldg(high_b + oc);
            const float bl = g_biaslow[p][oc];
            float* orow = out + (((size_t)b*C_OUT + oc)*OHW + oy)*OHW + oxb;
            #pragma unroll
            for (int j = 0; j < 8; ++j)
                orow[2*j] = acc[o][j] + (f[j] ? bh : bl);
        }
    }
}

// -------------------------------------------------------------------------
// Inputs (metadata order): x, mask, inv_mask, high_w, high_b,
//                          low1_w, low1_b, low2_w, low2_b
// inv_mask unused: mask is binary {0,1}, so inv = 1-m is implied by select.
// -------------------------------------------------------------------------
extern "C" void kernel_launch(void* const* d_in, const int* in_sizes, int n_in,
                              void* d_out, int out_size)
{
    const float* x      = (const float*)d_in[0];
    const float* mask   = (const float*)d_in[1];
    const float* high_w = (const float*)d_in[3];
    const float* high_b = (const float*)d_in[4];
    const float* low1_w = (const float*)d_in[5];
    const float* low1_b = (const float*)d_in[6];
    const float* low2_w = (const float*)d_in[7];
    const float* low2_b = (const float*)d_in[8];
    float* out = (float*)d_out;

    cudaFuncSetAttribute(tconv_main,
                         cudaFuncAttributeMaxDynamicSharedMemorySize, SMEM_BYTES);

    pack_kernel<<<dim3(2, 4), 256>>>(high_w, low1_w, low1_b, low2_w, low2_b);
    tconv_main<<<dim3(HW/TI, HW/TI, 4), 256, SMEM_BYTES>>>(x, mask, high_b, out);
}

// round 3
// speedup vs baseline: 3.5574x; 3.5574x over previous
#include <cuda_runtime.h>
#include <cuda_bf16.h>
#include <cstdint>

#define HW   256
#define OHW  512

// ---------------------------------------------------------------------------
// Packed weights, bf16 hi/lo split, pre-swizzled (SW128) B tiles:
// g_B[parity][tap][split][swz(n*128 + c*2)/2]; n<64 = high branch, n>=64 = low
// ---------------------------------------------------------------------------
__device__ __align__(16) __nv_bfloat16 g_B[4][4][2][128 * 64];
__device__ float g_biaslow[4][64];

static __device__ __forceinline__ uint32_t swz128(uint32_t off) {
    return off ^ ((off >> 3) & 0x70);
}

// ---------------------------------------------------------------------------
// Pack: fold low1(1x1) into low2, split fp32 -> bf16 hi/lo, swizzle into g_B.
// Parity p=(py,px); tap t: ty=t/ntx, tx=t%ntx;
//   ky = py ? (ty?0:2) : 1 ; kx = px ? (tx?0:2) : 1   (validated round 1)
// ---------------------------------------------------------------------------
__global__ void pack_kernel(const float* __restrict__ high_w,
                            const float* __restrict__ low1_w,
                            const float* __restrict__ low1_b,
                            const float* __restrict__ low2_w,
                            const float* __restrict__ low2_b)
{
    const int p = blockIdx.x, t = blockIdx.y;
    const int py = p >> 1, px = p & 1;
    const int nty = py ? 2 : 1, ntx = px ? 2 : 1;
    const int ntaps = nty * ntx;

    if (t < ntaps) {
        const int ty = t / ntx, tx = t % ntx;
        const int ky = py ? (ty ? 0 : 2) : 1;
        const int kx = px ? (tx ? 0 : 2) : 1;
        for (int idx = threadIdx.x; idx < 128 * 64; idx += blockDim.x) {
            const int n = idx >> 6, c = idx & 63;
            float w;
            if (n < 64) {
                w = high_w[((c * 64 + n) * 3 + ky) * 3 + kx];
            } else {
                const int o = n - 64;
                float s = 0.f;
                #pragma unroll
                for (int r = 0; r < 16; ++r)
                    s += low1_w[r * 64 + c] * low2_w[((r * 64 + o) * 3 + ky) * 3 + kx];
                w = s;
            }
            __nv_bfloat16 hi = __float2bfloat16(w);
            __nv_bfloat16 lo = __float2bfloat16(w - __bfloat162float(hi));
            const uint32_t sw = swz128((uint32_t)n * 128 + c * 2) >> 1;
            g_B[p][t][0][sw] = hi;
            g_B[p][t][1][sw] = lo;
        }
    }

    if (t == 0 && threadIdx.x < 64) {
        const int o = threadIdx.x;
        float s = low2_b[o];
        for (int ty = 0; ty < nty; ++ty)
            for (int tx = 0; tx < ntx; ++tx) {
                const int ky = py ? (ty ? 0 : 2) : 1;
                const int kx = px ? (tx ? 0 : 2) : 1;
                for (int r = 0; r < 16; ++r)
                    s += low1_b[r] * low2_w[((r * 64 + o) * 3 + ky) * 3 + kx];
            }
        g_biaslow[p][o] = s;
    }
}

// ---------------------------------------------------------------------------
// Warp-MMA helpers (baseline PTX, no arch-'a' features)
// ---------------------------------------------------------------------------
static __device__ __forceinline__ uint32_t smem_u32(const void* p) {
    uint32_t a;
    asm("{ .reg .u64 t; cvta.to.shared.u64 t, %1; cvt.u32.u64 %0, t; }" : "=r"(a) : "l"(p));
    return a;
}
static __device__ __forceinline__ void ldsm4(uint32_t r[4], uint32_t a) {
    asm volatile("ldmatrix.sync.aligned.m8n8.x4.shared.b16 {%0,%1,%2,%3}, [%4];"
        : "=r"(r[0]), "=r"(r[1]), "=r"(r[2]), "=r"(r[3]) : "r"(a));
}
static __device__ __forceinline__ void mma16816(float c[4], const uint32_t a[4],
                                                uint32_t b0, uint32_t b1) {
    asm volatile(
        "mma.sync.aligned.m16n8k16.row.col.f32.bf16.bf16.f32 "
        "{%0,%1,%2,%3}, {%4,%5,%6,%7}, {%8,%9}, {%0,%1,%2,%3};"
        : "+f"(c[0]), "+f"(c[1]), "+f"(c[2]), "+f"(c[3])
        : "r"(a[0]), "r"(a[1]), "r"(a[2]), "r"(a[3]), "r"(b0), "r"(b1));
}

// SMEM layout (64 KB): A_hi | A_lo | B_hi | B_lo ; reused as D[n][m] fp32 after
#define A_HI 0
#define A_LO 16384
#define B_HI 32768
#define B_LO 49152
#define SMEM_TOTAL 65536

// ---------------------------------------------------------------------------
// Main: one CTA = (batch, parity, 16x8 input tile) -> 128 pixels x 128 N.
// 4(M)x2(N) warps, warp tile 32x64, 3-pass bf16 split, SMEM-transposed epilogue.
// ---------------------------------------------------------------------------
__global__ __launch_bounds__(256, 2)
void tconv_mma(const float* __restrict__ x,
               const float* __restrict__ mask,
               const float* __restrict__ high_b,
               float* __restrict__ out)
{
    extern __shared__ char smem[];
    const uint32_t sb = smem_u32(smem);
    const int tid = threadIdx.x;
    const int lane = tid & 31;
    const int warp = tid >> 5;
    const int wm = warp & 3;          // 4 warps along M (pixels)
    const int wn = warp >> 2;         // 2 warps along N (channels*branch)
    const int b = blockIdx.z, p = blockIdx.y;
    const int py = p >> 1, px = p & 1;
    const int ntx = px ? 2 : 1;
    const int ntaps = (py ? 2 : 1) * ntx;
    const int x0 = (blockIdx.x & 15) * 16;
    const int y0 = (blockIdx.x >> 4) * 8;

    const float* xb = x + (size_t)b * 64 * HW * HW;

    float acc[2][8][4];
    #pragma unroll
    for (int i = 0; i < 2; ++i)
        #pragma unroll
        for (int j = 0; j < 8; ++j)
            #pragma unroll
            for (int k = 0; k < 4; ++k) acc[i][j][k] = 0.f;

    #pragma unroll 1
    for (int t = 0; t < ntaps; ++t) {
        const int ty = t / ntx, tx = t - ty * ntx;

        // ---- Build A chunk: 128 pixels x 64 ch, bf16 hi/lo, SW128 ----
        #pragma unroll 4
        for (int it = 0; it < 16; ++it) {
            const int idx = it * 256 + tid;
            const int m = idx & 127, cp = idx >> 7;
            const int my = m >> 4, mx = m & 15;
            const int iy = y0 + my + ty, ix = x0 + mx + tx;
            float f0 = 0.f, f1 = 0.f;
            if (iy < HW && ix < HW) {
                const float* xp = xb + ((size_t)(2 * cp) * HW + iy) * HW + ix;
                f0 = __ldg(xp);
                f1 = __ldg(xp + (size_t)HW * HW);
            }
            __nv_bfloat16 h0 = __float2bfloat16(f0), h1 = __float2bfloat16(f1);
            __nv_bfloat16 l0 = __float2bfloat16(f0 - __bfloat162float(h0));
            __nv_bfloat16 l1 = __float2bfloat16(f1 - __bfloat162float(h1));
            const uint32_t sw = swz128((uint32_t)m * 128 + cp * 4);
            const uint32_t hv = ((uint32_t)__bfloat16_as_ushort(h1) << 16) | __bfloat16_as_ushort(h0);
            const uint32_t lv = ((uint32_t)__bfloat16_as_ushort(l1) << 16) | __bfloat16_as_ushort(l0);
            *(uint32_t*)(smem + A_HI + sw) = hv;
            *(uint32_t*)(smem + A_LO + sw) = lv;
        }
        // ---- Copy B chunk (hi+lo, 32 KB, pre-swizzled) ----
        {
            const uint4* src = (const uint4*)&g_B[p][t][0][0];
            uint4* dst = (uint4*)(smem + B_HI);
            #pragma unroll
            for (int it = 0; it < 8; ++it) dst[it * 256 + tid] = src[it * 256 + tid];
        }
        __syncthreads();

        // ---- MMA over K=64 (4 k16 steps), 3 split passes fused per step ----
        #pragma unroll 1
        for (int ks = 0; ks < 4; ++ks) {
            uint32_t ah[2][4], al[2][4];
            const int arow = (lane & 15);
            const int akb = ks * 32 + ((lane >> 4) << 4);
            #pragma unroll
            for (int mf = 0; mf < 2; ++mf) {
                const uint32_t aoff = swz128((uint32_t)(wm * 32 + mf * 16 + arow) * 128 + akb);
                ldsm4(ah[mf], sb + A_HI + aoff);
                ldsm4(al[mf], sb + A_LO + aoff);
            }
            const int brow = (lane & 7) + ((lane >> 4) << 3);
            const int bkb = ks * 32 + (((lane >> 3) & 1) << 4);
            #pragma unroll
            for (int blk = 0; blk < 4; ++blk) {
                const uint32_t boff = swz128((uint32_t)(wn * 64 + blk * 16 + brow) * 128 + bkb);
                uint32_t bh[4], bl[4];
                ldsm4(bh, sb + B_HI + boff);
                ldsm4(bl, sb + B_LO + boff);
                #pragma unroll
                for (int mf = 0; mf < 2; ++mf) {
                    mma16816(acc[mf][blk * 2 + 0], ah[mf], bh[0], bh[1]);
                    mma16816(acc[mf][blk * 2 + 1], ah[mf], bh[2], bh[3]);
                    mma16816(acc[mf][blk * 2 + 0], al[mf], bh[0], bh[1]);
                    mma16816(acc[mf][blk * 2 + 1], al[mf], bh[2], bh[3]);
                    mma16816(acc[mf][blk * 2 + 0], ah[mf], bl[0], bl[1]);
                    mma16816(acc[mf][blk * 2 + 1], ah[mf], bl[2], bl[3]);
                }
            }
        }
        __syncthreads();   // before next tap overwrites A/B
    }

    // ---- Transpose accumulators into SMEM D[n][m] (xor-swizzled) ----
    #pragma unroll
    for (int mf = 0; mf < 2; ++mf)
        #pragma unroll
        for (int nf = 0; nf < 8; ++nf)
            #pragma unroll
            for (int r = 0; r < 4; ++r) {
                const int n = wn * 64 + nf * 8 + (lane & 3) * 2 + (r & 1);
                const int m = wm * 32 + mf * 16 + (lane >> 2) + (r >> 1) * 8;
                const uint32_t off = (uint32_t)n * 512 + (((uint32_t)m * 4) ^ ((n & 7) << 4));
                *(float*)(smem + off) = acc[mf][nf][r];
            }
    __syncthreads();

    // ---- Epilogue: mask-select branch, add bias, stride-2 stores ----
    {
        const int m = tid & 127;
        const int half = tid >> 7;
        const int my = m >> 4, mx = m & 15;
        const int oy = 2 * (y0 + my) + py;
        const int ox = 2 * (x0 + mx) + px;
        const float mv = __ldg(mask + ((size_t)b * OHW + oy) * OHW + ox);
        const bool f = (mv >= 0.5f);
        float* orow = out + ((size_t)b * 64 * OHW + oy) * OHW + ox;

        #pragma unroll 8
        for (int k = 0; k < 32; ++k) {
            const int oc = 2 * k + half;
            const uint32_t xr = ((oc & 7) << 4);
            const float dh = *(const float*)(smem + (uint32_t)oc * 512 + (((uint32_t)m * 4) ^ xr));
            const float dl = *(const float*)(smem + (uint32_t)(oc + 64) * 512 + (((uint32_t)m * 4) ^ xr));
            const float v = f ? (dh + __ldg(high_b + oc)) : (dl + g_biaslow[p][oc]);
            orow[(size_t)oc * OHW * OHW] = v;
        }
    }
}

// ---------------------------------------------------------------------------
// Inputs: x, mask, inv_mask, high_w, high_b, low1_w, low1_b, low2_w, low2_b
// ---------------------------------------------------------------------------
extern "C" void kernel_launch(void* const* d_in, const int* in_sizes, int n_in,
                              void* d_out, int out_size)
{
    const float* x      = (const float*)d_in[0];
    const float* mask   = (const float*)d_in[1];
    const float* high_w = (const float*)d_in[3];
    const float* high_b = (const float*)d_in[4];
    const float* low1_w = (const float*)d_in[5];
    const float* low1_b = (const float*)d_in[6];
    const float* low2_w = (const float*)d_in[7];
    const float* low2_b = (const float*)d_in[8];
    float* out = (float*)d_out;

    cudaFuncSetAttribute(tconv_mma,
                         cudaFuncAttributeMaxDynamicSharedMemorySize, SMEM_TOTAL);

    pack_kernel<<<dim3(4, 4), 256>>>(high_w, low1_w, low1_b, low2_w, low2_b);
    tconv_mma<<<dim3(512, 4, 4), 256, SMEM_TOTAL>>>(x, mask, high_b, out);
}

// round 4
// speedup vs baseline: 3.9498x; 1.1103x over previous
#include <cuda_runtime.h>
#include <cuda_fp16.h>
#include <cstdint>

#define HW   256
#define OHW  512
#define XP   257          // padded spatial dim (halo row/col of zeros)
#define XP2  (XP*XP)      // 66049

// ---------------------------------------------------------------------------
// Scratch: transposed/split input planes and packed weights.
// g_xh/g_xl: [b][y][x][c] fp16, 128B per (b,y,x) row, zero-padded at y/x==256.
// g_Bp: per (parity,tap) 128(n) x 64(c) fp16, SW128 pre-swizzled; n<64 high.
// ---------------------------------------------------------------------------
__device__ __align__(16) __half g_xh[4 * XP2 * 64];
__device__ __align__(16) __half g_xl[4 * XP2 * 64];
__device__ __align__(16) __half g_Bp[4][4][128 * 64];
__device__ float g_biaslow[4][64];

static __device__ __forceinline__ uint32_t swz128(uint32_t off) {
    return off ^ ((off >> 3) & 0x70);
}

// ---------------------------------------------------------------------------
// Prep 1: transpose x -> [b][y][x][c], split fp32 -> fp16 hi/lo, zero pad.
// ---------------------------------------------------------------------------
__global__ void prep_x(const float* __restrict__ x)
{
    __shared__ float tile[64][33];
    const int y  = blockIdx.x;            // 0..256
    const int x0 = blockIdx.y * 32;       // 0..256 step 32
    const int b  = blockIdx.z;
    const int tid = threadIdx.x;

    for (int i = tid; i < 64 * 32; i += 256) {
        const int c = i >> 5, xl = i & 31;
        const int xx = x0 + xl;
        float v = 0.f;
        if (y < HW && xx < HW)
            v = x[(((size_t)b * 64 + c) * HW + y) * HW + xx];
        tile[c][xl] = v;
    }
    __syncthreads();

    for (int i = tid; i < 32 * 64; i += 256) {
        const int xl = i >> 6, c = i & 63;
        const int xx = x0 + xl;
        if (xx > 256) continue;
        const float v = tile[c][xl];
        const __half h = __float2half(v);
        const __half l = __float2half(v - __half2float(h));
        const size_t o = ((size_t)b * XP2 + (size_t)y * XP + xx) * 64 + c;
        g_xh[o] = h;
        g_xl[o] = l;
    }
}

// ---------------------------------------------------------------------------
// Prep 2: fold low1(1x1) into low2, pack fp16 B tiles (SW128), fold biases.
// Parity p=(py,px); tap t: ty=t/ntx, tx=t%ntx;
//   ky = py ? (ty?0:2) : 1 ; kx = px ? (tx?0:2) : 1   (validated rounds 1,3)
// ---------------------------------------------------------------------------
__global__ void pack_kernel(const float* __restrict__ high_w,
                            const float* __restrict__ low1_w,
                            const float* __restrict__ low1_b,
                            const float* __restrict__ low2_w,
                            const float* __restrict__ low2_b)
{
    const int p = blockIdx.x, t = blockIdx.y;
    const int py = p >> 1, px = p & 1;
    const int nty = py ? 2 : 1, ntx = px ? 2 : 1;
    const int ntaps = nty * ntx;

    if (t < ntaps) {
        const int ty = t / ntx, tx = t % ntx;
        const int ky = py ? (ty ? 0 : 2) : 1;
        const int kx = px ? (tx ? 0 : 2) : 1;
        for (int idx = threadIdx.x; idx < 128 * 64; idx += blockDim.x) {
            const int n = idx >> 6, c = idx & 63;
            float w;
            if (n < 64) {
                w = high_w[((c * 64 + n) * 3 + ky) * 3 + kx];
            } else {
                const int o = n - 64;
                float s = 0.f;
                #pragma unroll
                for (int r = 0; r < 16; ++r)
                    s += low1_w[r * 64 + c] * low2_w[((r * 64 + o) * 3 + ky) * 3 + kx];
                w = s;
            }
            g_Bp[p][t][swz128((uint32_t)n * 128 + c * 2) >> 1] = __float2half(w);
        }
    }

    if (t == 0 && threadIdx.x < 64) {
        const int o = threadIdx.x;
        float s = low2_b[o];
        for (int ty = 0; ty < nty; ++ty)
            for (int tx = 0; tx < ntx; ++tx) {
                const int ky = py ? (ty ? 0 : 2) : 1;
                const int kx = px ? (tx ? 0 : 2) : 1;
                for (int r = 0; r < 16; ++r)
                    s += low1_b[r] * low2_w[((r * 64 + o) * 3 + ky) * 3 + kx];
            }
        g_biaslow[p][o] = s;
    }
}

// ---------------------------------------------------------------------------
// PTX helpers (baseline ISA only — no arch-'a' features; sm_103 ptxas-safe)
// ---------------------------------------------------------------------------
static __device__ __forceinline__ uint32_t smem_u32(const void* p) {
    uint32_t a;
    asm("{ .reg .u64 t; cvta.to.shared.u64 t, %1; cvt.u32.u64 %0, t; }" : "=r"(a) : "l"(p));
    return a;
}
static __device__ __forceinline__ void ldsm4(uint32_t r[4], uint32_t a) {
    asm volatile("ldmatrix.sync.aligned.m8n8.x4.shared.b16 {%0,%1,%2,%3}, [%4];"
        : "=r"(r[0]), "=r"(r[1]), "=r"(r[2]), "=r"(r[3]) : "r"(a));
}
static __device__ __forceinline__ void mma16816(float c[4], const uint32_t a[4],
                                                uint32_t b0, uint32_t b1) {
    asm volatile(
        "mma.sync.aligned.m16n8k16.row.col.f32.f16.f16.f32 "
        "{%0,%1,%2,%3}, {%4,%5,%6,%7}, {%8,%9}, {%0,%1,%2,%3};"
        : "+f"(c[0]), "+f"(c[1]), "+f"(c[2]), "+f"(c[3])
        : "r"(a[0]), "r"(a[1]), "r"(a[2]), "r"(a[3]), "r"(b0), "r"(b1));
}
#define CP16(dst, src) \
    asm volatile("cp.async.cg.shared.global [%0], [%1], 16;" :: "r"(dst), "l"(src))
#define CP_COMMIT() asm volatile("cp.async.commit_group;" ::: "memory")
#define CP_WAIT0()  asm volatile("cp.async.wait_group 0;" ::: "memory")
#define CP_WAIT1()  asm volatile("cp.async.wait_group 1;" ::: "memory")

// SMEM stages: A_hi(16K) | A_lo(16K) | B(16K) = 48K, double-buffered = 96K.
// Epilogue D[n][m] fp32 (64K) reuses the stage area.
#define A_HI   0
#define A_LO   16384
#define B_OFF  32768
#define STAGE  49152
#define SMEM_TOTAL (2 * STAGE)   // 98304

// ---------------------------------------------------------------------------
// Main: CTA = (batch, parity, 16x8 input tile) -> 128 pixels x 128 N.
// fp16 2-pass (A hi/lo x B), cp.async double-buffered tap pipeline.
// ---------------------------------------------------------------------------
__global__ __launch_bounds__(256, 2)
void tconv_mma(const float* __restrict__ mask,
               const float* __restrict__ high_b,
               float* __restrict__ out)
{
    extern __shared__ char smem[];
    const uint32_t sb = smem_u32(smem);
    const int tid = threadIdx.x;
    const int lane = tid & 31;
    const int warp = tid >> 5;
    const int wm = warp & 3;          // 4 warps along M
    const int wn = warp >> 2;         // 2 warps along N
    const int b = blockIdx.z, p = blockIdx.y;
    const int py = p >> 1, px = p & 1;
    const int ntx = px ? 2 : 1;
    const int ntaps = (py ? 2 : 1) * ntx;
    const int x0 = (blockIdx.x & 15) * 16;
    const int y0 = (blockIdx.x >> 4) * 8;

    // Per-thread cp.async assignment for A: row m = tid&127, split s = tid>>7
    const int am  = tid & 127;
    const int as  = tid >> 7;
    const int amy = am >> 4, amx = am & 15;
    const __half* axbase = (as ? g_xl : g_xh)
        + ((size_t)b * XP2 + (size_t)(y0 + amy) * XP + (x0 + amx)) * 64;
    const uint32_t adst0 = (uint32_t)as * 16384 + (uint32_t)am * 128;
    const uint32_t axr   = (uint32_t)(am & 7) << 4;

    float acc[2][8][4];
    #pragma unroll
    for (int i = 0; i < 2; ++i)
        #pragma unroll
        for (int j = 0; j < 8; ++j)
            #pragma unroll
            for (int k = 0; k < 4; ++k) acc[i][j][k] = 0.f;

    // ---- issue loads for tap t into stage buf ----
    auto issue = [&](int t, int buf) {
        const int ty = t / ntx, tx = t - ty * ntx;
        const char* srcA = (const char*)(axbase + ((size_t)ty * XP + tx) * 64);
        const uint32_t db = sb + buf * STAGE;
        const uint32_t ad = db + adst0;
        #pragma unroll
        for (int i = 0; i < 8; ++i)
            CP16(ad + (((uint32_t)i << 4) ^ axr), srcA + (i << 4));
        const char* srcB = (const char*)&g_Bp[p][t][0];
        const uint32_t bd = db + B_OFF;
        #pragma unroll
        for (int k = 0; k < 4; ++k)
            CP16(bd + (k * 256 + tid) * 16, srcB + (k * 256 + tid) * 16);
        CP_COMMIT();
    };

    issue(0, 0);

    #pragma unroll 1
    for (int t = 0; t < ntaps; ++t) {
        const int buf = t & 1;
        if (t + 1 < ntaps) { issue(t + 1, buf ^ 1); CP_WAIT1(); }
        else               { CP_WAIT0(); }
        __syncthreads();

        const uint32_t base = sb + buf * STAGE;
        #pragma unroll
        for (int ks = 0; ks < 4; ++ks) {
            uint32_t ah[2][4], al[2][4];
            const int arow = (lane & 15);
            const int akb = ks * 32 + ((lane >> 4) << 4);
            #pragma unroll
            for (int mf = 0; mf < 2; ++mf) {
                const uint32_t aoff = swz128((uint32_t)(wm * 32 + mf * 16 + arow) * 128 + akb);
                ldsm4(ah[mf], base + A_HI + aoff);
                ldsm4(al[mf], base + A_LO + aoff);
            }
            const int brow = (lane & 7) + ((lane >> 4) << 3);
            const int bkb = ks * 32 + (((lane >> 3) & 1) << 4);
            #pragma unroll
            for (int blk = 0; blk < 4; ++blk) {
                const uint32_t boff = swz128((uint32_t)(wn * 64 + blk * 16 + brow) * 128 + bkb);
                uint32_t bh[4];
                ldsm4(bh, base + B_OFF + boff);
                #pragma unroll
                for (int mf = 0; mf < 2; ++mf) {
                    mma16816(acc[mf][blk * 2 + 0], ah[mf], bh[0], bh[1]);
                    mma16816(acc[mf][blk * 2 + 1], ah[mf], bh[2], bh[3]);
                    mma16816(acc[mf][blk * 2 + 0], al[mf], bh[0], bh[1]);
                    mma16816(acc[mf][blk * 2 + 1], al[mf], bh[2], bh[3]);
                }
            }
        }
        __syncthreads();   // all warps done reading buf before it is re-filled
    }

    // ---- Transpose accumulators into SMEM D[n][m] (xor-swizzled) ----
    #pragma unroll
    for (int mf = 0; mf < 2; ++mf)
        #pragma unroll
        for (int nf = 0; nf < 8; ++nf)
            #pragma unroll
            for (int r = 0; r < 4; ++r) {
                const int n = wn * 64 + nf * 8 + (lane & 3) * 2 + (r & 1);
                const int m = wm * 32 + mf * 16 + (lane >> 2) + (r >> 1) * 8;
                const uint32_t off = (uint32_t)n * 512 + (((uint32_t)m * 4) ^ ((n & 7) << 4));
                *(float*)(smem + off) = acc[mf][nf][r];
            }
    __syncthreads();

    // ---- Epilogue: mask-select branch, add bias, stride-2 stores ----
    {
        const int m = tid & 127;
        const int half_ = tid >> 7;
        const int my = m >> 4, mx = m & 15;
        const int oy = 2 * (y0 + my) + py;
        const int ox = 2 * (x0 + mx) + px;
        const float mv = __ldg(mask + ((size_t)b * OHW + oy) * OHW + ox);
        const bool f = (mv >= 0.5f);
        float* orow = out + ((size_t)b * 64 * OHW + oy) * OHW + ox;

        #pragma unroll 8
        for (int k = 0; k < 32; ++k) {
            const int oc = 2 * k + half_;
            const uint32_t xr = ((oc & 7) << 4);
            const float dh = *(const float*)(smem + (uint32_t)oc * 512 + (((uint32_t)m * 4) ^ xr));
            const float dl = *(const float*)(smem + (uint32_t)(oc + 64) * 512 + (((uint32_t)m * 4) ^ xr));
            const float v = f ? (dh + __ldg(high_b + oc)) : (dl + g_biaslow[p][oc]);
            orow[(size_t)oc * OHW * OHW] = v;
        }
    }
}

// ---------------------------------------------------------------------------
// Inputs: x, mask, inv_mask, high_w, high_b, low1_w, low1_b, low2_w, low2_b
// ---------------------------------------------------------------------------
extern "C" void kernel_launch(void* const* d_in, const int* in_sizes, int n_in,
                              void* d_out, int out_size)
{
    const float* x      = (const float*)d_in[0];
    const float* mask   = (const float*)d_in[1];
    const float* high_w = (const float*)d_in[3];
    const float* high_b = (const float*)d_in[4];
    const float* low1_w = (const float*)d_in[5];
    const float* low1_b = (const float*)d_in[6];
    const float* low2_w = (const float*)d_in[7];
    const float* low2_b = (const float*)d_in[8];
    float* out = (float*)d_out;

    cudaFuncSetAttribute(tconv_mma,
                         cudaFuncAttributeMaxDynamicSharedMemorySize, SMEM_TOTAL);

    prep_x<<<dim3(XP, 9, 4), 256>>>(x);
    pack_kernel<<<dim3(4, 4), 256>>>(high_w, low1_w, low1_b, low2_w, low2_b);
    tconv_mma<<<dim3(512, 4, 4), 256, SMEM_TOTAL>>>(mask, high_b, out);
}

// round 5
// speedup vs baseline: 6.3061x; 1.5966x over previous
#include <cuda_runtime.h>
#include <cuda_fp16.h>
#include <cstdint>

#define HW   256
#define OHW  512
#define XP   257          // padded spatial dim (halo row/col of zeros)
#define XP2  (XP*XP)      // 66049

// ---------------------------------------------------------------------------
// g_xh: [b][y][x][c] fp16, 128B per (b,y,x), zero-padded at y/x==256.
// g_Bp: per (parity,tap) 128(n) x 64(c) fp16, SW128 pre-swizzled; n<64 high.
// ---------------------------------------------------------------------------
__device__ __align__(16) __half g_xh[4 * XP2 * 64];
__device__ __align__(16) __half g_Bp[4][4][128 * 64];
__device__ float g_biaslow[4][64];

static __device__ __forceinline__ uint32_t swz128(uint32_t off) {
    return off ^ ((off >> 3) & 0x70);
}

// ---------------------------------------------------------------------------
// Prep 1: transpose x -> [b][y][x][c] fp16, zero pad.
// ---------------------------------------------------------------------------
__global__ void prep_x(const float* __restrict__ x)
{
    __shared__ float tile[64][33];
    const int y  = blockIdx.x;            // 0..256
    const int x0 = blockIdx.y * 32;       // 0..256 step 32
    const int b  = blockIdx.z;
    const int tid = threadIdx.x;

    for (int i = tid; i < 64 * 32; i += 256) {
        const int c = i >> 5, xl = i & 31;
        const int xx = x0 + xl;
        float v = 0.f;
        if (y < HW && xx < HW)
            v = x[(((size_t)b * 64 + c) * HW + y) * HW + xx];
        tile[c][xl] = v;
    }
    __syncthreads();

    for (int i = tid; i < 32 * 64; i += 256) {
        const int xl = i >> 6, c = i & 63;
        const int xx = x0 + xl;
        if (xx > 256) continue;
        g_xh[((size_t)b * XP2 + (size_t)y * XP + xx) * 64 + c] =
            __float2half(tile[c][xl]);
    }
}

// ---------------------------------------------------------------------------
// Prep 2: fold low1(1x1) into low2, pack fp16 B tiles (SW128), fold biases.
// Parity p=(py,px); tap t: ty=t/ntx, tx=t%ntx;
//   ky = py ? (ty?0:2) : 1 ; kx = px ? (tx?0:2) : 1   (validated rounds 1,3,4)
// ---------------------------------------------------------------------------
__global__ void pack_kernel(const float* __restrict__ high_w,
                            const float* __restrict__ low1_w,
                            const float* __restrict__ low1_b,
                            const float* __restrict__ low2_w,
                            const float* __restrict__ low2_b)
{
    const int p = blockIdx.x, t = blockIdx.y;
    const int py = p >> 1, px = p & 1;
    const int nty = py ? 2 : 1, ntx = px ? 2 : 1;
    const int ntaps = nty * ntx;

    if (t < ntaps) {
        const int ty = t / ntx, tx = t % ntx;
        const int ky = py ? (ty ? 0 : 2) : 1;
        const int kx = px ? (tx ? 0 : 2) : 1;
        for (int idx = threadIdx.x; idx < 128 * 64; idx += blockDim.x) {
            const int n = idx >> 6, c = idx & 63;
            float w;
            if (n < 64) {
                w = high_w[((c * 64 + n) * 3 + ky) * 3 + kx];
            } else {
                const int o = n - 64;
                float s = 0.f;
                #pragma unroll
                for (int r = 0; r < 16; ++r)
                    s += low1_w[r * 64 + c] * low2_w[((r * 64 + o) * 3 + ky) * 3 + kx];
                w = s;
            }
            g_Bp[p][t][swz128((uint32_t)n * 128 + c * 2) >> 1] = __float2half(w);
        }
    }

    if (t == 0 && threadIdx.x < 64) {
        const int o = threadIdx.x;
        float s = low2_b[o];
        for (int ty = 0; ty < nty; ++ty)
            for (int tx = 0; tx < ntx; ++tx) {
                const int ky = py ? (ty ? 0 : 2) : 1;
                const int kx = px ? (tx ? 0 : 2) : 1;
                for (int r = 0; r < 16; ++r)
                    s += low1_b[r] * low2_w[((r * 64 + o) * 3 + ky) * 3 + kx];
            }
        g_biaslow[p][o] = s;
    }
}

// ---------------------------------------------------------------------------
// PTX helpers (baseline ISA only — sm_103 ptxas-safe)
// ---------------------------------------------------------------------------
static __device__ __forceinline__ uint32_t smem_u32(const void* p) {
    uint32_t a;
    asm("{ .reg .u64 t; cvta.to.shared.u64 t, %1; cvt.u32.u64 %0, t; }" : "=r"(a) : "l"(p));
    return a;
}
static __device__ __forceinline__ void ldsm4(uint32_t r[4], uint32_t a) {
    asm volatile("ldmatrix.sync.aligned.m8n8.x4.shared.b16 {%0,%1,%2,%3}, [%4];"
        : "=r"(r[0]), "=r"(r[1]), "=r"(r[2]), "=r"(r[3]) : "r"(a));
}
static __device__ __forceinline__ void mma16816(float c[4], const uint32_t a[4],
                                                uint32_t b0, uint32_t b1) {
    asm volatile(
        "mma.sync.aligned.m16n8k16.row.col.f32.f16.f16.f32 "
        "{%0,%1,%2,%3}, {%4,%5,%6,%7}, {%8,%9}, {%0,%1,%2,%3};"
        : "+f"(c[0]), "+f"(c[1]), "+f"(c[2]), "+f"(c[3])
        : "r"(a[0]), "r"(a[1]), "r"(a[2]), "r"(a[3]), "r"(b0), "r"(b1));
}
#define CP16(dst, src) \
    asm volatile("cp.async.cg.shared.global [%0], [%1], 16;" :: "r"(dst), "l"(src))
#define CP_COMMIT() asm volatile("cp.async.commit_group;" ::: "memory")
#define CP_WAIT0()  asm volatile("cp.async.wait_group 0;" ::: "memory")
#define CP_WAIT1()  asm volatile("cp.async.wait_group 1;" ::: "memory")

// SMEM: A halo 153 rows x 128B at 0 (19584B); B stages at 20480 / 36864.
// Epilogue D[n][m] fp32 (64KB) reuses everything after the final sync.
#define A_OFF   0
#define HALO_ROWS 153            // 9 x 17
#define B0_OFF  20480
#define B_STRIDE 16384
#define SMEM_TOTAL 65536

// ---------------------------------------------------------------------------
// Main: CTA = (batch, parity, 16x8 input tile) -> 128 pixels x 128 N.
// fp16 single pass; persistent halo A; B-only double-buffered pipeline.
// ---------------------------------------------------------------------------
__global__ __launch_bounds__(256, 2)
void tconv_mma(const float* __restrict__ mask,
               const float* __restrict__ high_b,
               float* __restrict__ out)
{
    extern __shared__ char smem[];
    const uint32_t sb = smem_u32(smem);
    const int tid = threadIdx.x;
    const int lane = tid & 31;
    const int warp = tid >> 5;
    const int wm = warp & 3;          // 4 warps along M
    const int wn = warp >> 2;         // 2 warps along N
    const int b = blockIdx.z, p = blockIdx.y;
    const int py = p >> 1, px = p & 1;
    const int ntx = px ? 2 : 1;
    const int ntaps = (py ? 2 : 1) * ntx;
    const int x0 = (blockIdx.x & 15) * 16;
    const int y0 = (blockIdx.x >> 4) * 8;

    // ---- fill A halo (153 rows x 128B) + B tap0; commit as group 0 ----
    {
        const __half* xbase = g_xh + ((size_t)b * XP2 + (size_t)y0 * XP + x0) * 64;
        #pragma unroll
        for (int i = 0; i < 5; ++i) {
            const int e = i * 256 + tid;           // 16B chunk index
            if (e < HALO_ROWS * 8) {
                const int hr = e >> 3, c16 = (e & 7) << 4;
                const int ry = hr / 17, rx = hr - ry * 17;
                const char* src = (const char*)(xbase + ((size_t)ry * XP + rx) * 64) + c16;
                CP16(sb + A_OFF + (uint32_t)hr * 128 + (c16 ^ ((hr & 7) << 4)), src);
            }
        }
        const char* srcB = (const char*)&g_Bp[p][0][0];
        #pragma unroll
        for (int k = 0; k < 4; ++k)
            CP16(sb + B0_OFF + (k * 256 + tid) * 16, srcB + (k * 256 + tid) * 16);
        CP_COMMIT();
    }

    float acc[2][8][4];
    #pragma unroll
    for (int i = 0; i < 2; ++i)
        #pragma unroll
        for (int j = 0; j < 8; ++j)
            #pragma unroll
            for (int k = 0; k < 4; ++k) acc[i][j][k] = 0.f;

    #pragma unroll 1
    for (int t = 0; t < ntaps; ++t) {
        if (t + 1 < ntaps) {
            const char* srcB = (const char*)&g_Bp[p][t + 1][0];
            const uint32_t bd = sb + B0_OFF + ((t + 1) & 1) * B_STRIDE;
            #pragma unroll
            for (int k = 0; k < 4; ++k)
                CP16(bd + (k * 256 + tid) * 16, srcB + (k * 256 + tid) * 16);
            CP_COMMIT();
            CP_WAIT1();
        } else {
            CP_WAIT0();
        }
        __syncthreads();

        const int ty = t / ntx, tx = t - ty * ntx;
        const uint32_t bbase = sb + B0_OFF + (t & 1) * B_STRIDE;

        #pragma unroll
        for (int ks = 0; ks < 4; ++ks) {
            uint32_t ah[2][4];
            const int arow = lane & 15;
            const int akb = ks * 32 + ((lane >> 4) << 4);
            #pragma unroll
            for (int mf = 0; mf < 2; ++mf) {
                const int m = wm * 32 + mf * 16 + arow;
                const int hr = ((m >> 4) + ty) * 17 + (m & 15) + tx;
                ldsm4(ah[mf], sb + A_OFF + (uint32_t)hr * 128
                              + ((uint32_t)akb ^ ((uint32_t)(hr & 7) << 4)));
            }
            const int brow = (lane & 7) + ((lane >> 4) << 3);
            const int bkb = ks * 32 + (((lane >> 3) & 1) << 4);
            #pragma unroll
            for (int blk = 0; blk < 4; ++blk) {
                uint32_t bh[4];
                ldsm4(bh, bbase + swz128((uint32_t)(wn * 64 + blk * 16 + brow) * 128 + bkb));
                #pragma unroll
                for (int mf = 0; mf < 2; ++mf) {
                    mma16816(acc[mf][blk * 2 + 0], ah[mf], bh[0], bh[1]);
                    mma16816(acc[mf][blk * 2 + 1], ah[mf], bh[2], bh[3]);
                }
            }
        }
        __syncthreads();   // all warps done with B buf before it is re-filled
    }

    // ---- Transpose accumulators into SMEM D[n][m] (xor-swizzled) ----
    #pragma unroll
    for (int mf = 0; mf < 2; ++mf)
        #pragma unroll
        for (int nf = 0; nf < 8; ++nf)
            #pragma unroll
            for (int r = 0; r < 4; ++r) {
                const int n = wn * 64 + nf * 8 + (lane & 3) * 2 + (r & 1);
                const int m = wm * 32 + mf * 16 + (lane >> 2) + (r >> 1) * 8;
                const uint32_t off = (uint32_t)n * 512 + (((uint32_t)m * 4) ^ ((n & 7) << 4));
                *(float*)(smem + off) = acc[mf][nf][r];
            }
    __syncthreads();

    // ---- Epilogue: mask-select branch, add bias, stride-2 stores ----
    {
        const int m = tid & 127;
        const int half_ = tid >> 7;
        const int my = m >> 4, mx = m & 15;
        const int oy = 2 * (y0 + my) + py;
        const int ox = 2 * (x0 + mx) + px;
        const float mv = __ldg(mask + ((size_t)b * OHW + oy) * OHW + ox);
        const bool f = (mv >= 0.5f);
        float* orow = out + ((size_t)b * 64 * OHW + oy) * OHW + ox;

        #pragma unroll 8
        for (int k = 0; k < 32; ++k) {
            const int oc = 2 * k + half_;
            const uint32_t xr = ((oc & 7) << 4);
            const float dh = *(const float*)(smem + (uint32_t)oc * 512 + (((uint32_t)m * 4) ^ xr));
            const float dl = *(const float*)(smem + (uint32_t)(oc + 64) * 512 + (((uint32_t)m * 4) ^ xr));
            const float v = f ? (dh + __ldg(high_b + oc)) : (dl + g_biaslow[p][oc]);
            orow[(size_t)oc * OHW * OHW] = v;
        }
    }
}

// ---------------------------------------------------------------------------
// Inputs: x, mask, inv_mask, high_w, high_b, low1_w, low1_b, low2_w, low2_b
// ---------------------------------------------------------------------------
extern "C" void kernel_launch(void* const* d_in, const int* in_sizes, int n_in,
                              void* d_out, int out_size)
{
    const float* x      = (const float*)d_in[0];
    const float* mask   = (const float*)d_in[1];
    const float* high_w = (const float*)d_in[3];
    const float* high_b = (const float*)d_in[4];
    const float* low1_w = (const float*)d_in[5];
    const float* low1_b = (const float*)d_in[6];
    const float* low2_w = (const float*)d_in[7];
    const float* low2_b = (const float*)d_in[8];
    float* out = (float*)d_out;

    cudaFuncSetAttribute(tconv_mma,
                         cudaFuncAttributeMaxDynamicSharedMemorySize, SMEM_TOTAL);

    prep_x<<<dim3(XP, 9, 4), 256>>>(x);
    pack_kernel<<<dim3(4, 4), 256>>>(high_w, low1_w, low1_b, low2_w, low2_b);
    tconv_mma<<<dim3(512, 4, 4), 256, SMEM_TOTAL>>>(mask, high_b, out);
}